// round 6
// baseline (speedup 1.0000x reference)
#include <cuda_runtime.h>

#define NUM_USERS 100000
#define NUM_ITEMS 50000
#define N_NODES   150000
#define DIM       64
#define NUM_EDGES 4000000

// Scratch (allocation-free rule: __device__ globals).
__device__ float g_bufA[N_NODES * DIM];
__device__ float g_bufB[N_NODES * DIM];
__device__ int2  g_edges[NUM_EDGES];       // interleaved {col, val-bits}
__device__ int   g_hist[N_NODES];
__device__ int   g_rowptr[N_NODES + 1];
__device__ int   g_cursor[N_NODES];

// -------------------------------------------------------------------------
// Kernel 1: zero histogram.
// -------------------------------------------------------------------------
__global__ void lgcn_zero_hist()
{
    int i = blockIdx.x * blockDim.x + threadIdx.x;
    if (i < N_NODES) g_hist[i] = 0;
}

// -------------------------------------------------------------------------
// Kernel 2: degree histogram, 8 edges/thread (2x int4 loads).
// -------------------------------------------------------------------------
__global__ void lgcn_hist(const int* __restrict__ edge_row)
{
    int i = blockIdx.x * blockDim.x + threadIdx.x;
    if (i >= NUM_EDGES / 8) return;
    int4 r0 = ((const int4*)edge_row)[i * 2];
    int4 r1 = ((const int4*)edge_row)[i * 2 + 1];
    atomicAdd(&g_hist[r0.x], 1);
    atomicAdd(&g_hist[r0.y], 1);
    atomicAdd(&g_hist[r0.z], 1);
    atomicAdd(&g_hist[r0.w], 1);
    atomicAdd(&g_hist[r1.x], 1);
    atomicAdd(&g_hist[r1.y], 1);
    atomicAdd(&g_hist[r1.z], 1);
    atomicAdd(&g_hist[r1.w], 1);
}

// -------------------------------------------------------------------------
// Kernel 3: single-block exclusive scan -> row_ptr + cursor.
// -------------------------------------------------------------------------
__global__ void lgcn_scan()
{
    const int T = 1024;
    const int CHUNK = (N_NODES + T - 1) / T;   // 147
    __shared__ int s_part[T];

    int t   = threadIdx.x;
    int beg = t * CHUNK;
    int end = min(beg + CHUNK, N_NODES);

    int sum = 0;
    for (int i = beg; i < end; i++) sum += g_hist[i];
    s_part[t] = sum;
    __syncthreads();

    for (int off = 1; off < T; off <<= 1) {
        int v = (t >= off) ? s_part[t - off] : 0;
        __syncthreads();
        s_part[t] += v;
        __syncthreads();
    }

    int run = s_part[t] - sum;
    for (int i = beg; i < end; i++) {
        g_rowptr[i] = run;
        g_cursor[i] = run;
        run += g_hist[i];
    }
    if (t == 0) g_rowptr[N_NODES] = NUM_EDGES;
}

// -------------------------------------------------------------------------
// Kernel 4: scatter edges into row-sorted interleaved array, 8 edges/thread.
// -------------------------------------------------------------------------
__global__ void lgcn_scatter(const float* __restrict__ edge_vals,
                             const int*   __restrict__ edge_row,
                             const int*   __restrict__ edge_col)
{
    int i = blockIdx.x * blockDim.x + threadIdx.x;
    if (i >= NUM_EDGES / 8) return;
    int4   r0 = ((const int4*)edge_row)[i * 2];
    int4   r1 = ((const int4*)edge_row)[i * 2 + 1];
    int4   c0 = ((const int4*)edge_col)[i * 2];
    int4   c1 = ((const int4*)edge_col)[i * 2 + 1];
    float4 v0 = ((const float4*)edge_vals)[i * 2];
    float4 v1 = ((const float4*)edge_vals)[i * 2 + 1];

    int p0 = atomicAdd(&g_cursor[r0.x], 1);
    int p1 = atomicAdd(&g_cursor[r0.y], 1);
    int p2 = atomicAdd(&g_cursor[r0.z], 1);
    int p3 = atomicAdd(&g_cursor[r0.w], 1);
    int p4 = atomicAdd(&g_cursor[r1.x], 1);
    int p5 = atomicAdd(&g_cursor[r1.y], 1);
    int p6 = atomicAdd(&g_cursor[r1.z], 1);
    int p7 = atomicAdd(&g_cursor[r1.w], 1);

    g_edges[p0] = make_int2(c0.x, __float_as_int(v0.x));
    g_edges[p1] = make_int2(c0.y, __float_as_int(v0.y));
    g_edges[p2] = make_int2(c0.z, __float_as_int(v0.z));
    g_edges[p3] = make_int2(c0.w, __float_as_int(v0.w));
    g_edges[p4] = make_int2(c1.x, __float_as_int(v1.x));
    g_edges[p5] = make_int2(c1.y, __float_as_int(v1.y));
    g_edges[p6] = make_int2(c1.z, __float_as_int(v1.z));
    g_edges[p7] = make_int2(c1.w, __float_as_int(v1.w));
}

// -------------------------------------------------------------------------
// Kernel 5: warp-per-node CSR gather (R4 shape + deeper MLP).
// float2 lanes (32 lanes = 64 dims), smem-staged edge meta, unroll 16,
// two accumulators to split the FFMA chain, default (L1-cached) loads.
// MODE 0: layer1, virtual concat input, out = emb + acc.
// MODE 1: out += acc.   MODE 2: out = (out + acc) * 0.25.
// -------------------------------------------------------------------------
template<int MODE>
__global__ void __launch_bounds__(256)
lgcn_gather(const float* __restrict__ cur,
            const float* __restrict__ user_emb,
            const float* __restrict__ item_emb,
            float*       __restrict__ nxt,
            float*       __restrict__ out)
{
    __shared__ int2 s_edges[8][32];
    const int wslot = threadIdx.x >> 5;
    const int lane  = threadIdx.x & 31;
    const int node  = blockIdx.x * 8 + wslot;
    if (node >= N_NODES) return;

    const int start = g_rowptr[node];
    const int end   = g_rowptr[node + 1];

    float2 acc0 = make_float2(0.f, 0.f);
    float2 acc1 = make_float2(0.f, 0.f);

    for (int base = start; base < end; base += 32) {
        int idx = base + lane;
        if (idx < end) s_edges[wslot][lane] = g_edges[idx];
        __syncwarp();
        const int n = min(32, end - base);
        #pragma unroll 16
        for (int j = 0; j < n; j++) {
            int2  cv = s_edges[wslot][j];
            float vj = __int_as_float(cv.y);
            const float2* src;
            if (MODE == 0) {
                const float2* us = (const float2*)user_emb + (size_t)cv.x * (DIM / 2);
                const float2* is = (const float2*)item_emb
                                   + (size_t)(cv.x - NUM_USERS) * (DIM / 2);
                src = (cv.x < NUM_USERS) ? us : is;   // branchless SEL
            } else {
                src = (const float2*)cur + (size_t)cv.x * (DIM / 2);
            }
            float2 x = src[lane];
            if (j & 1) {
                acc1.x += vj * x.x;
                acc1.y += vj * x.y;
            } else {
                acc0.x += vj * x.x;
                acc0.y += vj * x.y;
            }
        }
        __syncwarp();
    }

    float2 acc = make_float2(acc0.x + acc1.x, acc0.y + acc1.y);

    float2* o = (float2*)(out + (size_t)node * DIM);
    if (MODE == 0) {
        const float2* e = (node < NUM_USERS)
            ? (const float2*)user_emb + (size_t)node * (DIM / 2)
            : (const float2*)item_emb + (size_t)(node - NUM_USERS) * (DIM / 2);
        float2 ev = e[lane];
        o[lane] = make_float2(ev.x + acc.x, ev.y + acc.y);
        ((float2*)(nxt + (size_t)node * DIM))[lane] = acc;
    } else if (MODE == 1) {
        float2 a = o[lane];
        a.x += acc.x; a.y += acc.y;
        o[lane] = a;
        ((float2*)(nxt + (size_t)node * DIM))[lane] = acc;
    } else {
        float2 a = o[lane];
        a.x = (a.x + acc.x) * 0.25f;
        a.y = (a.y + acc.y) * 0.25f;
        o[lane] = a;
    }
}

// -------------------------------------------------------------------------
// Launch: 7 kernels, graph-capturable, no sync, no alloc.
// -------------------------------------------------------------------------
extern "C" void kernel_launch(void* const* d_in, const int* in_sizes, int n_in,
                              void* d_out, int out_size)
{
    const float* user_emb  = (const float*)d_in[0];
    const float* item_emb  = (const float*)d_in[1];
    const float* edge_vals = (const float*)d_in[2];
    const int*   edge_row  = (const int*)d_in[3];
    const int*   edge_col  = (const int*)d_in[4];
    float* out = (float*)d_out;

    float *bufA, *bufB;
    cudaGetSymbolAddress((void**)&bufA, g_bufA);
    cudaGetSymbolAddress((void**)&bufB, g_bufB);

    const int zero_grid = (N_NODES + 255) / 256;
    const int e8_grid   = (NUM_EDGES / 8 + 255) / 256;
    const int gather_grid = (N_NODES + 7) / 8;   // 8 warps/block

    // Build CSR (re-done every replay: deterministic, no cached state).
    lgcn_zero_hist<<<zero_grid, 256>>>();
    lgcn_hist<<<e8_grid, 256>>>(edge_row);
    lgcn_scan<<<1, 1024>>>();
    lgcn_scatter<<<e8_grid, 256>>>(edge_vals, edge_row, edge_col);

    // 3 propagation layers, accumulation fused.
    lgcn_gather<0><<<gather_grid, 256>>>(nullptr, user_emb, item_emb, bufB, out);
    lgcn_gather<1><<<gather_grid, 256>>>(bufB,    user_emb, item_emb, bufA, out);
    lgcn_gather<2><<<gather_grid, 256>>>(bufA,    user_emb, item_emb, nullptr, out);
}

// round 7
// speedup vs baseline: 1.1425x; 1.1425x over previous
#include <cuda_runtime.h>
#include <cuda_fp16.h>

#define NUM_USERS 100000
#define NUM_ITEMS 50000
#define N_NODES   150000
#define DIM       64
#define NUM_EDGES 4000000

// Scratch (allocation-free rule: __device__ globals).
// Propagation ping-pong buffers in fp16 (halves gather L2 traffic).
__device__ __half2 g_bufA[N_NODES * DIM / 2];
__device__ __half2 g_bufB[N_NODES * DIM / 2];
__device__ int2    g_edges[NUM_EDGES];      // interleaved {col, val-bits}
__device__ int     g_hist[N_NODES];
__device__ int     g_rowptr[N_NODES + 1];
__device__ int     g_cursor[N_NODES];

// -------------------------------------------------------------------------
// Kernel 1: convert concat(user,item) embeddings -> fp16 bufA; zero hist.
// Each thread converts 8 floats (2x float4 -> 1x uint4 of half2).
// -------------------------------------------------------------------------
__global__ void lgcn_convert(const float* __restrict__ user_emb,
                             const float* __restrict__ item_emb)
{
    int i = blockIdx.x * blockDim.x + threadIdx.x;
    const int total8 = N_NODES * DIM / 8;
    if (i < total8) {
        const int user8 = NUM_USERS * DIM / 8;
        const float4* s = (i < user8)
            ? (const float4*)user_emb + 2 * (size_t)i
            : (const float4*)item_emb + 2 * (size_t)(i - user8);
        float4 a = s[0];
        float4 b = s[1];
        __half2 h0 = __floats2half2_rn(a.x, a.y);
        __half2 h1 = __floats2half2_rn(a.z, a.w);
        __half2 h2 = __floats2half2_rn(b.x, b.y);
        __half2 h3 = __floats2half2_rn(b.z, b.w);
        uint4 p;
        p.x = *(unsigned int*)&h0;
        p.y = *(unsigned int*)&h1;
        p.z = *(unsigned int*)&h2;
        p.w = *(unsigned int*)&h3;
        ((uint4*)g_bufA)[i] = p;
    }
    if (i < N_NODES) g_hist[i] = 0;
}

// -------------------------------------------------------------------------
// Kernel 2: degree histogram, 8 edges/thread (2x int4 loads).
// -------------------------------------------------------------------------
__global__ void lgcn_hist(const int* __restrict__ edge_row)
{
    int i = blockIdx.x * blockDim.x + threadIdx.x;
    if (i >= NUM_EDGES / 8) return;
    int4 r0 = ((const int4*)edge_row)[i * 2];
    int4 r1 = ((const int4*)edge_row)[i * 2 + 1];
    atomicAdd(&g_hist[r0.x], 1);
    atomicAdd(&g_hist[r0.y], 1);
    atomicAdd(&g_hist[r0.z], 1);
    atomicAdd(&g_hist[r0.w], 1);
    atomicAdd(&g_hist[r1.x], 1);
    atomicAdd(&g_hist[r1.y], 1);
    atomicAdd(&g_hist[r1.z], 1);
    atomicAdd(&g_hist[r1.w], 1);
}

// -------------------------------------------------------------------------
// Kernel 3: single-block exclusive scan -> row_ptr + cursor.
// -------------------------------------------------------------------------
__global__ void lgcn_scan()
{
    const int T = 1024;
    const int CHUNK = (N_NODES + T - 1) / T;   // 147
    __shared__ int s_part[T];

    int t   = threadIdx.x;
    int beg = t * CHUNK;
    int end = min(beg + CHUNK, N_NODES);

    int sum = 0;
    for (int i = beg; i < end; i++) sum += g_hist[i];
    s_part[t] = sum;
    __syncthreads();

    for (int off = 1; off < T; off <<= 1) {
        int v = (t >= off) ? s_part[t - off] : 0;
        __syncthreads();
        s_part[t] += v;
        __syncthreads();
    }

    int run = s_part[t] - sum;
    for (int i = beg; i < end; i++) {
        g_rowptr[i] = run;
        g_cursor[i] = run;
        run += g_hist[i];
    }
    if (t == 0) g_rowptr[N_NODES] = NUM_EDGES;
}

// -------------------------------------------------------------------------
// Kernel 4: scatter edges into row-sorted interleaved array, 8 edges/thread.
// -------------------------------------------------------------------------
__global__ void lgcn_scatter(const float* __restrict__ edge_vals,
                             const int*   __restrict__ edge_row,
                             const int*   __restrict__ edge_col)
{
    int i = blockIdx.x * blockDim.x + threadIdx.x;
    if (i >= NUM_EDGES / 8) return;
    int4   r0 = ((const int4*)edge_row)[i * 2];
    int4   r1 = ((const int4*)edge_row)[i * 2 + 1];
    int4   c0 = ((const int4*)edge_col)[i * 2];
    int4   c1 = ((const int4*)edge_col)[i * 2 + 1];
    float4 v0 = ((const float4*)edge_vals)[i * 2];
    float4 v1 = ((const float4*)edge_vals)[i * 2 + 1];

    int p0 = atomicAdd(&g_cursor[r0.x], 1);
    int p1 = atomicAdd(&g_cursor[r0.y], 1);
    int p2 = atomicAdd(&g_cursor[r0.z], 1);
    int p3 = atomicAdd(&g_cursor[r0.w], 1);
    int p4 = atomicAdd(&g_cursor[r1.x], 1);
    int p5 = atomicAdd(&g_cursor[r1.y], 1);
    int p6 = atomicAdd(&g_cursor[r1.z], 1);
    int p7 = atomicAdd(&g_cursor[r1.w], 1);

    g_edges[p0] = make_int2(c0.x, __float_as_int(v0.x));
    g_edges[p1] = make_int2(c0.y, __float_as_int(v0.y));
    g_edges[p2] = make_int2(c0.z, __float_as_int(v0.z));
    g_edges[p3] = make_int2(c0.w, __float_as_int(v0.w));
    g_edges[p4] = make_int2(c1.x, __float_as_int(v1.x));
    g_edges[p5] = make_int2(c1.y, __float_as_int(v1.y));
    g_edges[p6] = make_int2(c1.z, __float_as_int(v1.z));
    g_edges[p7] = make_int2(c1.w, __float_as_int(v1.w));
}

// -------------------------------------------------------------------------
// Kernel 5: warp-per-node CSR gather, fp16 rows (128 B = 1 wavefront/edge).
// R4-proven loop shape: smem-staged meta, unroll 8, single fp32 accumulator.
// MODE 0: out = emb_f32 + acc; nxt = half(acc).
// MODE 1: out += acc;          nxt = half(acc).
// MODE 2: out = (out + acc) * 0.25.
// -------------------------------------------------------------------------
template<int MODE>
__global__ void __launch_bounds__(256)
lgcn_gather(const __half2* __restrict__ cur,
            const float*   __restrict__ user_emb,
            const float*   __restrict__ item_emb,
            __half2*       __restrict__ nxt,
            float*         __restrict__ out)
{
    __shared__ int2 s_edges[8][32];
    const int wslot = threadIdx.x >> 5;
    const int lane  = threadIdx.x & 31;
    const int node  = blockIdx.x * 8 + wslot;
    if (node >= N_NODES) return;

    const int start = g_rowptr[node];
    const int end   = g_rowptr[node + 1];

    float2 acc = make_float2(0.f, 0.f);

    for (int base = start; base < end; base += 32) {
        int idx = base + lane;
        if (idx < end) s_edges[wslot][lane] = g_edges[idx];
        __syncwarp();
        const int n = min(32, end - base);
        #pragma unroll 8
        for (int j = 0; j < n; j++) {
            int2  cv = s_edges[wslot][j];
            float vj = __int_as_float(cv.y);
            __half2 x = cur[(size_t)cv.x * (DIM / 2) + lane];
            float2 xf = __half22float2(x);
            acc.x += vj * xf.x;
            acc.y += vj * xf.y;
        }
        __syncwarp();
    }

    float2* o = (float2*)(out + (size_t)node * DIM);
    if (MODE == 0) {
        const float2* e = (node < NUM_USERS)
            ? (const float2*)user_emb + (size_t)node * (DIM / 2)
            : (const float2*)item_emb + (size_t)(node - NUM_USERS) * (DIM / 2);
        float2 ev = e[lane];
        o[lane] = make_float2(ev.x + acc.x, ev.y + acc.y);
        nxt[(size_t)node * (DIM / 2) + lane] = __floats2half2_rn(acc.x, acc.y);
    } else if (MODE == 1) {
        float2 a = o[lane];
        a.x += acc.x; a.y += acc.y;
        o[lane] = a;
        nxt[(size_t)node * (DIM / 2) + lane] = __floats2half2_rn(acc.x, acc.y);
    } else {
        float2 a = o[lane];
        a.x = (a.x + acc.x) * 0.25f;
        a.y = (a.y + acc.y) * 0.25f;
        o[lane] = a;
    }
}

// -------------------------------------------------------------------------
// Launch: 7 kernels, graph-capturable, no sync, no alloc.
// -------------------------------------------------------------------------
extern "C" void kernel_launch(void* const* d_in, const int* in_sizes, int n_in,
                              void* d_out, int out_size)
{
    const float* user_emb  = (const float*)d_in[0];
    const float* item_emb  = (const float*)d_in[1];
    const float* edge_vals = (const float*)d_in[2];
    const int*   edge_row  = (const int*)d_in[3];
    const int*   edge_col  = (const int*)d_in[4];
    float* out = (float*)d_out;

    __half2 *bufA, *bufB;
    cudaGetSymbolAddress((void**)&bufA, g_bufA);
    cudaGetSymbolAddress((void**)&bufB, g_bufB);

    const int conv_grid = (N_NODES * DIM / 8 + 255) / 256;
    const int e8_grid   = (NUM_EDGES / 8 + 255) / 256;
    const int gather_grid = (N_NODES + 7) / 8;   // 8 warps/block

    // Build fp16 input + CSR (re-done every replay: deterministic).
    lgcn_convert<<<conv_grid, 256>>>(user_emb, item_emb);
    lgcn_hist<<<e8_grid, 256>>>(edge_row);
    lgcn_scan<<<1, 1024>>>();
    lgcn_scatter<<<e8_grid, 256>>>(edge_vals, edge_row, edge_col);

    // 3 propagation layers, accumulation fused.
    lgcn_gather<0><<<gather_grid, 256>>>(bufA, user_emb, item_emb, bufB, out);
    lgcn_gather<1><<<gather_grid, 256>>>(bufB, user_emb, item_emb, bufA, out);
    lgcn_gather<2><<<gather_grid, 256>>>(bufA, user_emb, item_emb, nullptr, out);
}